// round 14
// baseline (speedup 1.0000x reference)
#include <cuda_runtime.h>
#include <cuda_bf16.h>
#include <cstdint>

// EAM potential — smem coefficient-table kernel.
// Per block (8 rows, one batch): build two tables indexed by j
//   tbl[t_i][j] = {u1,c1,u2,c2} for pair type (t_i + t_j)   (NT==2)
// Inner loop per element: LDS.128 + 2 FMA + 2 EX2 + cutoff + 2 FMA.
// No per-element selects, no per-element type loads.
// Lane-0 per warp adds row energy to per-batch int64 fixed-point atomics
// (exact, order-independent => deterministic); last block writes out.
//
// Inputs (metadata order):
//   0 distances [B,N,N] f32   1 A[NPT]   2 p[NPT]   3 xi[NPT]   4 q[NPT]
//   5 r0[NPT]  6 cut_a[NPT]   7 cut_b[NPT]  8 emb_scale[NT]  9 offset[NT]
//  10 types [B,N] i32        11 pair_types (UNUSED, recomputed from types)

#define MAX_B   64
#define FIX_SCALE 268435456.0   // 2^28

__device__ long long     g_energy_fix[MAX_B];   // zero-init; reset each run
__device__ int           g_count[MAX_B];
__device__ unsigned int  g_ticket;

__device__ __forceinline__ float ex2_approx(float x) {
    float y; asm("ex2.approx.f32 %0, %1;" : "=f"(y) : "f"(x)); return y;
}
__device__ __forceinline__ float fma_sat(float a, float b, float c) {
    float y; asm("fma.rn.sat.f32 %0, %1, %2, %3;" : "=f"(y) : "f"(a), "f"(b), "f"(c)); return y;
}
__device__ __forceinline__ int pair_type(int ti, int tj, int NT) {
    int tmin = min(ti, tj), tmax = max(ti, tj);
    return tmin * NT - (tmin * (tmin - 1)) / 2 + (tmax - tmin);
}

// 32-byte distance load (8 floats); .v4.b64 form required for evict_last.
struct F8 { float f[8]; };
template <bool EVL>
__device__ __forceinline__ F8 ldg_f8(const float* ptr) {
    unsigned long long d0, d1, d2, d3;
    if (EVL)
        asm("ld.global.nc.L2::evict_last.v4.b64 {%0,%1,%2,%3}, [%4];"
            : "=l"(d0), "=l"(d1), "=l"(d2), "=l"(d3) : "l"(ptr));
    else
        asm("ld.global.nc.v4.b64 {%0,%1,%2,%3}, [%4];"
            : "=l"(d0), "=l"(d1), "=l"(d2), "=l"(d3) : "l"(ptr));
    F8 r;
    r.f[0] = __uint_as_float((unsigned)d0); r.f[1] = __uint_as_float((unsigned)(d0 >> 32));
    r.f[2] = __uint_as_float((unsigned)d1); r.f[3] = __uint_as_float((unsigned)(d1 >> 32));
    r.f[4] = __uint_as_float((unsigned)d2); r.f[5] = __uint_as_float((unsigned)(d2 >> 32));
    r.f[6] = __uint_as_float((unsigned)d3); r.f[7] = __uint_as_float((unsigned)(d3 >> 32));
    return r;
}

// ───────────────────── fast path: smem coefficient tables ─────────────────────
// NV8 = N/8. Block = 8 warps = 8 consecutive rows of one batch.

template <int NV8, bool EVL>
__global__ void __launch_bounds__(256)
eam_smem_kernel(const float* __restrict__ dist,      // [B,N,N]
                const int*   __restrict__ types,     // [B,N]
                const float* __restrict__ A,  const float* __restrict__ p,
                const float* __restrict__ xi, const float* __restrict__ q,
                const float* __restrict__ r0, const float* __restrict__ cut_a,
                const float* __restrict__ cut_b,
                const float* __restrict__ emb_scale,
                const float* __restrict__ offset,
                int B, float* __restrict__ out)
{
    constexpr int NN = NV8 * 8;

    __shared__ float4 tbl[2 * NN];                 // [t_i][j] -> {u1,c1,u2,c2}
    __shared__ float  preU1[4], preC1[4], preU2[4], preC2[4], preIB[4], preNA[4];
    __shared__ int    uniflag;

    const int tid     = threadIdx.x;
    const int lane    = tid & 31;
    const int w       = tid >> 5;
    const int rowBase = blockIdx.x * 8;
    const int b       = rowBase / NN;              // all 8 rows in same batch (N%8==0)
    const int* __restrict__ trowp = types + (size_t)b * NN;

    // per-block pair-type params (3 pair types for NT==2), computed once
    if (tid < 3) {
        const int pt = tid;
        const float L2E = 1.4426950408889634f;
        const float pv = p[pt], qv = q[pt], r0v = r0[pt];
        const float av = cut_a[pt], bv = cut_b[pt];
        const float ib = 1.0f / (bv - av);
        preU1[pt] = -pv * L2E / r0v;
        preC1[pt] =  pv * L2E + __log2f(A[pt]);
        preU2[pt] = -2.0f * qv * L2E / r0v;
        preC2[pt] =  2.0f * qv * L2E + 2.0f * __log2f(xi[pt]);
        preIB[pt] = ib;
        preNA[pt] = -av * ib;
    }
    __syncthreads();
    if (tid == 0) {
        uniflag = (preIB[0] == preIB[1]) && (preIB[1] == preIB[2]) &&
                  (preNA[0] == preNA[1]) && (preNA[1] == preNA[2]);
    }
    // build the two coefficient tables (one LDG of types per entry)
    for (int j = tid; j < NN; j += 256) {
        const int tj = trowp[j];
        tbl[j]      = make_float4(preU1[tj],     preC1[tj],     preU2[tj],     preC2[tj]);
        tbl[NN + j] = make_float4(preU1[tj + 1], preC1[tj + 1], preU2[tj + 1], preC2[tj + 1]);
    }
    __syncthreads();

    const int row = rowBase + w;
    const int t_i = trowp[row - b * NN];
    const float* __restrict__ drow = dist + (size_t)row * NN;
    const float4* __restrict__ T   = tbl + (t_i ? NN : 0);

    float sphiA = 0.f, srhoA = 0.f, sphiB = 0.f, srhoB = 0.f;

    if (uniflag) {
        // uniform cutoff across pair types: ib/na in registers, no selects
        const float IB = preIB[0], NA = preNA[0];
        #pragma unroll
        for (int k = 0; k < NV8 / 32; k++) {
            const int v8 = lane + k * 32;
            const F8 r8 = ldg_f8<EVL>(drow + v8 * 8);
            #pragma unroll
            for (int e = 0; e < 8; e++) {
                const float  r  = r8.f[e];
                const float4 P  = T[v8 * 8 + e];
                const float  x  = fma_sat(r, IB, NA);
                const float  fc = fmaf(x * x, fmaf(2.0f, x, -3.0f), 1.0f);
                const float  e1 = ex2_approx(fmaf(P.x, r, P.y));
                const float  e2 = ex2_approx(fmaf(P.z, r, P.w));
                if (e < 4) { sphiA = fmaf(fc, e1, sphiA); srhoA = fmaf(fc, e2, srhoA); }
                else       { sphiB = fmaf(fc, e1, sphiB); srhoB = fmaf(fc, e2, srhoB); }
            }
        }
    } else {
        // generic cutoff: per-element select of ib/na from registers
        const float IB0 = preIB[t_i], IB1 = preIB[t_i + 1];
        const float NA0 = preNA[t_i], NA1 = preNA[t_i + 1];
        const int4* __restrict__ trow4 = reinterpret_cast<const int4*>(trowp);
        #pragma unroll
        for (int k = 0; k < NV8 / 32; k++) {
            const int v8 = lane + k * 32;
            const F8   r8 = ldg_f8<EVL>(drow + v8 * 8);
            const int4 tA = trow4[2 * v8];
            const int4 tB = trow4[2 * v8 + 1];
            const int  tt[8] = {tA.x, tA.y, tA.z, tA.w, tB.x, tB.y, tB.z, tB.w};
            #pragma unroll
            for (int e = 0; e < 8; e++) {
                const bool   s  = tt[e] != 0;
                const float  r  = r8.f[e];
                const float4 P  = T[v8 * 8 + e];
                const float  x  = fma_sat(r, s ? IB1 : IB0, s ? NA1 : NA0);
                const float  fc = fmaf(x * x, fmaf(2.0f, x, -3.0f), 1.0f);
                const float  e1 = ex2_approx(fmaf(P.x, r, P.y));
                const float  e2 = ex2_approx(fmaf(P.z, r, P.w));
                if (e < 4) { sphiA = fmaf(fc, e1, sphiA); srhoA = fmaf(fc, e2, srhoA); }
                else       { sphiB = fmaf(fc, e1, sphiB); srhoB = fmaf(fc, e2, srhoB); }
            }
        }
    }

    float sphi = sphiA + sphiB;
    float srho = srhoA + srhoB;
    #pragma unroll
    for (int o = 16; o > 0; o >>= 1) {
        sphi += __shfl_down_sync(0xFFFFFFFFu, sphi, o);
        srho += __shfl_down_sync(0xFFFFFFFFu, srho, o);
    }
    if (lane == 0) {
        const float emb = fmaf(-emb_scale[t_i], sqrtf(srho), offset[t_i]);
        const float ae  = fmaf(0.5f, sphi, emb);
        atomicAdd(reinterpret_cast<unsigned long long*>(&g_energy_fix[b]),
                  (unsigned long long)(long long)__float2ll_rn(ae * (float)FIX_SCALE));
        if (t_i >= 0) atomicAdd(&g_count[b], 1);
    }

    // ── last-block ticket → tiny finalize ──
    __syncthreads();
    __shared__ unsigned int rank_s;
    if (tid == 0) {
        __threadfence();
        rank_s = atomicAdd(&g_ticket, 1u);
    }
    __syncthreads();
    if (rank_s != gridDim.x - 1u) return;

    if (tid == 0) __threadfence();
    __syncthreads();
    if (tid < (unsigned)B) {
        const float E = (float)((double)g_energy_fix[tid] / FIX_SCALE);
        out[2 * tid]     = E;
        out[2 * tid + 1] = E / (float)g_count[tid];
        g_energy_fix[tid] = 0;             // reset for next graph replay
        g_count[tid]      = 0;
    }
    __syncthreads();
    if (tid == 0) g_ticket = 0u;
}

// ───────────────────────── generic fallback ─────────────────────────

__global__ void __launch_bounds__(256)
eam_warp_kernel(const float* __restrict__ dist, const int* __restrict__ types,
                const float* __restrict__ A,  const float* __restrict__ p,
                const float* __restrict__ xi, const float* __restrict__ q,
                const float* __restrict__ r0, const float* __restrict__ cut_a,
                const float* __restrict__ cut_b,
                const float* __restrict__ emb_scale,
                const float* __restrict__ offset, int N, int NT, int BN)
{
    const int lane = threadIdx.x & 31;
    const int row  = blockIdx.x * (blockDim.x >> 5) + (threadIdx.x >> 5);
    if (row >= BN) return;
    const int b    = row / N;
    const int t_i  = types[row];
    const float L2E = 1.4426950408889634f;
    float sphi = 0.0f, srho = 0.0f;
    for (int j = lane; j < N; j += 32) {
        const int pt = pair_type(t_i, types[(size_t)b * N + j], NT);
        const float r = dist[(size_t)row * N + j];
        const float ib = 1.0f / (cut_b[pt] - cut_a[pt]);
        const float x = fma_sat(r, ib, -cut_a[pt] * ib);
        const float fc = fmaf(x * x, fmaf(2.0f, x, -3.0f), 1.0f);
        const float rn = r / r0[pt] - 1.0f;
        sphi = fmaf(A[pt] * fc, ex2_approx(-p[pt] * L2E * rn), sphi);
        srho = fmaf(xi[pt] * xi[pt] * fc, ex2_approx(-2.0f * q[pt] * L2E * rn), srho);
    }
    #pragma unroll
    for (int o = 16; o > 0; o >>= 1) {
        sphi += __shfl_down_sync(0xFFFFFFFFu, sphi, o);
        srho += __shfl_down_sync(0xFFFFFFFFu, srho, o);
    }
    if (lane == 0) {
        const float emb = fmaf(-emb_scale[t_i], sqrtf(srho), offset[t_i]);
        const float ae  = fmaf(0.5f, sphi, emb);
        atomicAdd(reinterpret_cast<unsigned long long*>(&g_energy_fix[b]),
                  (unsigned long long)(long long)__float2ll_rn(ae * (float)FIX_SCALE));
        if (t_i >= 0) atomicAdd(&g_count[b], 1);
    }
}

__global__ void eam_finalize_kernel(float* __restrict__ out, int B)
{
    const int i = threadIdx.x;
    if (i < B) {
        const float E = (float)((double)g_energy_fix[i] / FIX_SCALE);
        out[2 * i]     = E;
        out[2 * i + 1] = E / (float)g_count[i];
        g_energy_fix[i] = 0;
        g_count[i]      = 0;
    }
}

// ───────────────────────────── launcher ─────────────────────────────

extern "C" void kernel_launch(void* const* d_in, const int* in_sizes, int n_in,
                              void* d_out, int out_size)
{
    const float* dist      = (const float*)d_in[0];
    const float* A         = (const float*)d_in[1];
    const float* p         = (const float*)d_in[2];
    const float* xi        = (const float*)d_in[3];
    const float* q         = (const float*)d_in[4];
    const float* r0        = (const float*)d_in[5];
    const float* cut_a     = (const float*)d_in[6];
    const float* cut_b     = (const float*)d_in[7];
    const float* emb_scale = (const float*)d_in[8];
    const float* offset    = (const float*)d_in[9];
    const int*   types     = (const int*)d_in[10];
    float* out = (float*)d_out;

    const long long dist_sz  = in_sizes[0];   // B*N*N
    const long long types_sz = in_sizes[10];  // B*N
    const int N   = (int)(dist_sz / types_sz);
    const int B   = (int)(types_sz / N);
    const int NT  = in_sizes[8];
    const int NPT = in_sizes[1];
    const int BN  = B * N;

    const bool aligned32 = ((uintptr_t)dist & 31u) == 0;
    const bool fast = (NT == 2) && (NPT >= 3) && (B >= 1) && (B <= MAX_B) &&
                      (BN % 8 == 0) && aligned32 &&
                      (N == 1024 || N == 512);
    const bool evl = (dist_sz * 4ll) <= (96ll << 20);   // fits in L2

    if (fast) {
        const int nblocks = BN / 8;
        if (N == 1024) {
            if (evl) eam_smem_kernel<128, true ><<<nblocks, 256>>>(dist, types,
                A, p, xi, q, r0, cut_a, cut_b, emb_scale, offset, B, out);
            else     eam_smem_kernel<128, false><<<nblocks, 256>>>(dist, types,
                A, p, xi, q, r0, cut_a, cut_b, emb_scale, offset, B, out);
        } else {
            if (evl) eam_smem_kernel<64, true ><<<nblocks, 256>>>(dist, types,
                A, p, xi, q, r0, cut_a, cut_b, emb_scale, offset, B, out);
            else     eam_smem_kernel<64, false><<<nblocks, 256>>>(dist, types,
                A, p, xi, q, r0, cut_a, cut_b, emb_scale, offset, B, out);
        }
    } else {
        const int warps_per_block = 8;
        const int nblocks = (BN + warps_per_block - 1) / warps_per_block;
        eam_warp_kernel<<<nblocks, warps_per_block * 32>>>(
            dist, types, A, p, xi, q, r0, cut_a, cut_b, emb_scale, offset,
            N, NT, BN);
        eam_finalize_kernel<<<1, 64>>>(out, B);
    }
}

// round 15
// speedup vs baseline: 2.2097x; 2.2097x over previous
#include <cuda_runtime.h>
#include <cuda_bf16.h>
#include <cstdint>

// EAM potential — smem coefficient-table kernel, TRANSPOSED (conflict-free).
// Table layout [t_i][e][v8]: element j = v8*8+e stored at slot e*NV8+v8, so
// lane L reads T[e*NV8 + L + 32k] -> consecutive 16B per lane, zero conflicts,
// e-offset is a compile-time immediate.
// Inner loop/element: LDS.128 + 2 FMA + 2 EX2 + FFMA.SAT + 2 FMA + 2 FMA.
// Per-batch int64 fixed-point atomics (exact, order-independent =>
// deterministic); last block (ticket) writes [B,2] and resets scratch.
//
// Inputs (metadata order):
//   0 distances [B,N,N] f32   1 A[NPT]   2 p[NPT]   3 xi[NPT]   4 q[NPT]
//   5 r0[NPT]  6 cut_a[NPT]   7 cut_b[NPT]  8 emb_scale[NT]  9 offset[NT]
//  10 types [B,N] i32        11 pair_types (UNUSED, recomputed from types)

#define MAX_B   64
#define FIX_SCALE 268435456.0   // 2^28

__device__ long long     g_energy_fix[MAX_B];   // zero-init; reset each run
__device__ int           g_count[MAX_B];
__device__ unsigned int  g_ticket;

__device__ __forceinline__ float ex2_approx(float x) {
    float y; asm("ex2.approx.f32 %0, %1;" : "=f"(y) : "f"(x)); return y;
}
__device__ __forceinline__ float fma_sat(float a, float b, float c) {
    float y; asm("fma.rn.sat.f32 %0, %1, %2, %3;" : "=f"(y) : "f"(a), "f"(b), "f"(c)); return y;
}
__device__ __forceinline__ int pair_type(int ti, int tj, int NT) {
    int tmin = min(ti, tj), tmax = max(ti, tj);
    return tmin * NT - (tmin * (tmin - 1)) / 2 + (tmax - tmin);
}

// 32-byte distance load (8 floats); .v4.b64 form required for evict_last.
struct F8 { float f[8]; };
template <bool EVL>
__device__ __forceinline__ F8 ldg_f8(const float* ptr) {
    unsigned long long d0, d1, d2, d3;
    if (EVL)
        asm("ld.global.nc.L2::evict_last.v4.b64 {%0,%1,%2,%3}, [%4];"
            : "=l"(d0), "=l"(d1), "=l"(d2), "=l"(d3) : "l"(ptr));
    else
        asm("ld.global.nc.v4.b64 {%0,%1,%2,%3}, [%4];"
            : "=l"(d0), "=l"(d1), "=l"(d2), "=l"(d3) : "l"(ptr));
    F8 r;
    r.f[0] = __uint_as_float((unsigned)d0); r.f[1] = __uint_as_float((unsigned)(d0 >> 32));
    r.f[2] = __uint_as_float((unsigned)d1); r.f[3] = __uint_as_float((unsigned)(d1 >> 32));
    r.f[4] = __uint_as_float((unsigned)d2); r.f[5] = __uint_as_float((unsigned)(d2 >> 32));
    r.f[6] = __uint_as_float((unsigned)d3); r.f[7] = __uint_as_float((unsigned)(d3 >> 32));
    return r;
}

// ─────────────── fast path: transposed smem coefficient tables ───────────────
// NV8 = N/8. Block = 8 warps = 8 consecutive rows of one batch.

template <int NV8, bool EVL>
__global__ void __launch_bounds__(256)
eam_smem_kernel(const float* __restrict__ dist,      // [B,N,N]
                const int*   __restrict__ types,     // [B,N]
                const float* __restrict__ A,  const float* __restrict__ p,
                const float* __restrict__ xi, const float* __restrict__ q,
                const float* __restrict__ r0, const float* __restrict__ cut_a,
                const float* __restrict__ cut_b,
                const float* __restrict__ emb_scale,
                const float* __restrict__ offset,
                int B, float* __restrict__ out)
{
    constexpr int NN = NV8 * 8;

    __shared__ float4 tbl[2 * NN];   // [t_i][e][v8]: slot = t_i*NN + e*NV8 + v8
    __shared__ float  preU1[4], preC1[4], preU2[4], preC2[4], preIB[4], preNA[4];
    __shared__ int    uniflag;

    const int tid     = threadIdx.x;
    const int lane    = tid & 31;
    const int w       = tid >> 5;
    const int rowBase = blockIdx.x * 8;
    const int b       = rowBase / NN;              // all 8 rows in same batch
    const int* __restrict__ trowp = types + (size_t)b * NN;

    // per-block pair-type params (3 pair types for NT==2), computed once
    if (tid < 3) {
        const int pt = tid;
        const float L2E = 1.4426950408889634f;
        const float pv = p[pt], qv = q[pt], r0v = r0[pt];
        const float av = cut_a[pt], bv = cut_b[pt];
        const float ib = 1.0f / (bv - av);
        preU1[pt] = -pv * L2E / r0v;
        preC1[pt] =  pv * L2E + __log2f(A[pt]);
        preU2[pt] = -2.0f * qv * L2E / r0v;
        preC2[pt] =  2.0f * qv * L2E + 2.0f * __log2f(xi[pt]);
        preIB[pt] = ib;
        preNA[pt] = -av * ib;
    }
    if (tid == 224) {   // different warp than tid<3; resolved by the barrier
        // placeholder slot (keeps warp divergence trivial)
    }
    __syncthreads();
    if (tid == 0) {
        uniflag = (preIB[0] == preIB[1]) && (preIB[1] == preIB[2]) &&
                  (preNA[0] == preNA[1]) && (preNA[1] == preNA[2]);
    }
    // build transposed tables: slot-major loop -> conflict-free STS
    for (int s = tid; s < NN; s += 256) {
        const int v8 = s % NV8;
        const int e  = s / NV8;
        const int j  = v8 * 8 + e;
        const int tj = trowp[j];
        tbl[s]      = make_float4(preU1[tj],     preC1[tj],     preU2[tj],     preC2[tj]);
        tbl[NN + s] = make_float4(preU1[tj + 1], preC1[tj + 1], preU2[tj + 1], preC2[tj + 1]);
    }
    __syncthreads();

    const int row = rowBase + w;
    const int t_i = trowp[row - b * NN];
    const float* __restrict__ drow = dist + (size_t)row * NN;
    const float4* __restrict__ T   = tbl + (t_i ? NN : 0);

    float sphiA = 0.f, srhoA = 0.f, sphiB = 0.f, srhoB = 0.f;

#define EAM_BODY(e, r, P, SP, SR, IBv, NAv)                                    \
    {                                                                          \
        const float x  = fma_sat(r, IBv, NAv);                                 \
        const float fc = fmaf(x * x, fmaf(2.0f, x, -3.0f), 1.0f);              \
        const float e1 = ex2_approx(fmaf(P.x, r, P.y));                        \
        const float e2 = ex2_approx(fmaf(P.z, r, P.w));                        \
        SP = fmaf(fc, e1, SP);                                                 \
        SR = fmaf(fc, e2, SR);                                                 \
    }

    if (uniflag) {
        const float IB = preIB[0], NA = preNA[0];
        #pragma unroll
        for (int k = 0; k < NV8 / 32; k++) {
            const int v8 = lane + k * 32;
            const F8 r8 = ldg_f8<EVL>(drow + v8 * 8);
            #pragma unroll
            for (int e = 0; e < 8; e++) {
                const float4 P = T[e * NV8 + v8];   // conflict-free, imm offset
                if (e < 4) EAM_BODY(e, r8.f[e], P, sphiA, srhoA, IB, NA)
                else       EAM_BODY(e, r8.f[e], P, sphiB, srhoB, IB, NA)
            }
        }
    } else {
        const float IB0 = preIB[t_i], IB1 = preIB[t_i + 1];
        const float NA0 = preNA[t_i], NA1 = preNA[t_i + 1];
        const int4* __restrict__ trow4 = reinterpret_cast<const int4*>(trowp);
        #pragma unroll
        for (int k = 0; k < NV8 / 32; k++) {
            const int v8 = lane + k * 32;
            const F8   r8 = ldg_f8<EVL>(drow + v8 * 8);
            const int4 tA = trow4[2 * v8];
            const int4 tB = trow4[2 * v8 + 1];
            const int  tt[8] = {tA.x, tA.y, tA.z, tA.w, tB.x, tB.y, tB.z, tB.w};
            #pragma unroll
            for (int e = 0; e < 8; e++) {
                const bool  s   = tt[e] != 0;
                const float IBv = s ? IB1 : IB0;
                const float NAv = s ? NA1 : NA0;
                const float4 P  = T[e * NV8 + v8];
                if (e < 4) EAM_BODY(e, r8.f[e], P, sphiA, srhoA, IBv, NAv)
                else       EAM_BODY(e, r8.f[e], P, sphiB, srhoB, IBv, NAv)
            }
        }
    }
#undef EAM_BODY

    float sphi = sphiA + sphiB;
    float srho = srhoA + srhoB;
    #pragma unroll
    for (int o = 16; o > 0; o >>= 1) {
        sphi += __shfl_down_sync(0xFFFFFFFFu, sphi, o);
        srho += __shfl_down_sync(0xFFFFFFFFu, srho, o);
    }
    if (lane == 0) {
        const float emb = fmaf(-emb_scale[t_i], sqrtf(srho), offset[t_i]);
        const float ae  = fmaf(0.5f, sphi, emb);
        atomicAdd(reinterpret_cast<unsigned long long*>(&g_energy_fix[b]),
                  (unsigned long long)(long long)__float2ll_rn(ae * (float)FIX_SCALE));
        if (t_i >= 0) atomicAdd(&g_count[b], 1);
    }

    // ── last-block ticket → tiny finalize ──
    __syncthreads();
    __shared__ unsigned int rank_s;
    if (tid == 0) {
        __threadfence();
        rank_s = atomicAdd(&g_ticket, 1u);
    }
    __syncthreads();
    if (rank_s != gridDim.x - 1u) return;

    if (tid == 0) __threadfence();
    __syncthreads();
    if (tid < (unsigned)B) {
        const float E = (float)((double)g_energy_fix[tid] / FIX_SCALE);
        out[2 * tid]     = E;
        out[2 * tid + 1] = E / (float)g_count[tid];
        g_energy_fix[tid] = 0;             // reset for next graph replay
        g_count[tid]      = 0;
    }
    __syncthreads();
    if (tid == 0) g_ticket = 0u;
}

// ───────────────────────── generic fallback ─────────────────────────

__global__ void __launch_bounds__(256)
eam_warp_kernel(const float* __restrict__ dist, const int* __restrict__ types,
                const float* __restrict__ A,  const float* __restrict__ p,
                const float* __restrict__ xi, const float* __restrict__ q,
                const float* __restrict__ r0, const float* __restrict__ cut_a,
                const float* __restrict__ cut_b,
                const float* __restrict__ emb_scale,
                const float* __restrict__ offset, int N, int NT, int BN)
{
    const int lane = threadIdx.x & 31;
    const int row  = blockIdx.x * (blockDim.x >> 5) + (threadIdx.x >> 5);
    if (row >= BN) return;
    const int b    = row / N;
    const int t_i  = types[row];
    const float L2E = 1.4426950408889634f;
    float sphi = 0.0f, srho = 0.0f;
    for (int j = lane; j < N; j += 32) {
        const int pt = pair_type(t_i, types[(size_t)b * N + j], NT);
        const float r = dist[(size_t)row * N + j];
        const float ib = 1.0f / (cut_b[pt] - cut_a[pt]);
        const float x = fma_sat(r, ib, -cut_a[pt] * ib);
        const float fc = fmaf(x * x, fmaf(2.0f, x, -3.0f), 1.0f);
        const float rn = r / r0[pt] - 1.0f;
        sphi = fmaf(A[pt] * fc, ex2_approx(-p[pt] * L2E * rn), sphi);
        srho = fmaf(xi[pt] * xi[pt] * fc, ex2_approx(-2.0f * q[pt] * L2E * rn), srho);
    }
    #pragma unroll
    for (int o = 16; o > 0; o >>= 1) {
        sphi += __shfl_down_sync(0xFFFFFFFFu, sphi, o);
        srho += __shfl_down_sync(0xFFFFFFFFu, srho, o);
    }
    if (lane == 0) {
        const float emb = fmaf(-emb_scale[t_i], sqrtf(srho), offset[t_i]);
        const float ae  = fmaf(0.5f, sphi, emb);
        atomicAdd(reinterpret_cast<unsigned long long*>(&g_energy_fix[b]),
                  (unsigned long long)(long long)__float2ll_rn(ae * (float)FIX_SCALE));
        if (t_i >= 0) atomicAdd(&g_count[b], 1);
    }
}

__global__ void eam_finalize_kernel(float* __restrict__ out, int B)
{
    const int i = threadIdx.x;
    if (i < B) {
        const float E = (float)((double)g_energy_fix[i] / FIX_SCALE);
        out[2 * i]     = E;
        out[2 * i + 1] = E / (float)g_count[i];
        g_energy_fix[i] = 0;
        g_count[i]      = 0;
    }
}

// ───────────────────────────── launcher ─────────────────────────────

extern "C" void kernel_launch(void* const* d_in, const int* in_sizes, int n_in,
                              void* d_out, int out_size)
{
    const float* dist      = (const float*)d_in[0];
    const float* A         = (const float*)d_in[1];
    const float* p         = (const float*)d_in[2];
    const float* xi        = (const float*)d_in[3];
    const float* q         = (const float*)d_in[4];
    const float* r0        = (const float*)d_in[5];
    const float* cut_a     = (const float*)d_in[6];
    const float* cut_b     = (const float*)d_in[7];
    const float* emb_scale = (const float*)d_in[8];
    const float* offset    = (const float*)d_in[9];
    const int*   types     = (const int*)d_in[10];
    float* out = (float*)d_out;

    const long long dist_sz  = in_sizes[0];   // B*N*N
    const long long types_sz = in_sizes[10];  // B*N
    const int N   = (int)(dist_sz / types_sz);
    const int B   = (int)(types_sz / N);
    const int NT  = in_sizes[8];
    const int NPT = in_sizes[1];
    const int BN  = B * N;

    const bool aligned32 = ((uintptr_t)dist & 31u) == 0;
    const bool fast = (NT == 2) && (NPT >= 3) && (B >= 1) && (B <= MAX_B) &&
                      (BN % 8 == 0) && aligned32 &&
                      (N == 1024 || N == 512);
    const bool evl = (dist_sz * 4ll) <= (96ll << 20);   // fits in L2

    if (fast) {
        const int nblocks = BN / 8;
        if (N == 1024) {
            if (evl) eam_smem_kernel<128, true ><<<nblocks, 256>>>(dist, types,
                A, p, xi, q, r0, cut_a, cut_b, emb_scale, offset, B, out);
            else     eam_smem_kernel<128, false><<<nblocks, 256>>>(dist, types,
                A, p, xi, q, r0, cut_a, cut_b, emb_scale, offset, B, out);
        } else {
            if (evl) eam_smem_kernel<64, true ><<<nblocks, 256>>>(dist, types,
                A, p, xi, q, r0, cut_a, cut_b, emb_scale, offset, B, out);
            else     eam_smem_kernel<64, false><<<nblocks, 256>>>(dist, types,
                A, p, xi, q, r0, cut_a, cut_b, emb_scale, offset, B, out);
        }
    } else {
        const int warps_per_block = 8;
        const int nblocks = (BN + warps_per_block - 1) / warps_per_block;
        eam_warp_kernel<<<nblocks, warps_per_block * 32>>>(
            dist, types, A, p, xi, q, r0, cut_a, cut_b, emb_scale, offset,
            N, NT, BN);
        eam_finalize_kernel<<<1, 64>>>(out, B);
    }
}

// round 17
// speedup vs baseline: 3.3769x; 1.5282x over previous
#include <cuda_runtime.h>
#include <cuda_bf16.h>
#include <cstdint>

// EAM potential — symmetric-tile kernel (NT==2 fast path).
// phi_ij == phi_ji and rho_ij == rho_ji exactly (symmetric distances, pair
// type depends on unordered pair), so only diagonal + upper 128x128 tiles are
// computed; off-diagonal tiles credit both row i and column j.
// Per-atom phi/rho accumulate in int64 fixed-point global atomics (exact,
// order-independent => deterministic). Per-batch ticket: last block of each
// batch finalizes that batch (emb + energy sums) and resets its scratch.
//
// Inputs (metadata order):
//   0 distances [B,N,N] f32   1 A[NPT]   2 p[NPT]   3 xi[NPT]   4 q[NPT]
//   5 r0[NPT]  6 cut_a[NPT]   7 cut_b[NPT]  8 emb_scale[NT]  9 offset[NT]
//  10 types [B,N] i32        11 pair_types (UNUSED, recomputed from types)

#define MAX_B   64
#define MAX_BN  65536
#define FIX_SCALE 268435456.0   // 2^28

__device__ unsigned long long g_phi[MAX_BN];    // zero-init; reset by finalizer
__device__ unsigned long long g_rho[MAX_BN];
__device__ unsigned int       g_ticket_b[MAX_B];
// fallback scratch
__device__ long long g_energy_fix[MAX_B];
__device__ int       g_count[MAX_B];

__device__ __forceinline__ float ex2_approx(float x) {
    float y; asm("ex2.approx.f32 %0, %1;" : "=f"(y) : "f"(x)); return y;
}
__device__ __forceinline__ float fma_sat(float a, float b, float c) {
    float y; asm("fma.rn.sat.f32 %0, %1, %2, %3;" : "=f"(y) : "f"(a), "f"(b), "f"(c)); return y;
}
__device__ __forceinline__ int pair_type(int ti, int tj, int NT) {
    int tmin = min(ti, tj), tmax = max(ti, tj);
    return tmin * NT - (tmin * (tmin - 1)) / 2 + (tmax - tmin);
}
__device__ __forceinline__ unsigned long long f2fix(float v) {
    return (unsigned long long)(long long)__float2ll_rn(v * (float)FIX_SCALE);
}

// ───────────────────────── fast path: symmetric tiles ─────────────────────────

struct TileSmem {
    float2 srow[128][33];     // per-(row, lane) partial sums; pad kills conflicts
    float  scolphi[128];
    float  scolrho[128];
    float  preU1[4], preC1[4], preU2[4], preC2[4], preIB[4], preNA[4];
    int    rowt[128];
};

template <bool DIAG>
__device__ __forceinline__ void tile_work(
    TileSmem& S, const float* __restrict__ dbase,  // row w*16 slice for this lane
    const int4 tj4, int w, int lane, size_t rowN)  // rowN = N (row stride)
{
    float colphi[4] = {0.f, 0.f, 0.f, 0.f};
    float colrho[4] = {0.f, 0.f, 0.f, 0.f};
    const int tjs[4] = {tj4.x, tj4.y, tj4.z, tj4.w};

    #pragma unroll
    for (int pass = 0; pass < 2; pass++) {
        // per-slot coefficients for pt = pass + tj_e (hoisted out of row loop)
        float U1e[4], C1e[4], U2e[4], C2e[4], IBe[4], NAe[4];
        #pragma unroll
        for (int e = 0; e < 4; e++) {
            const int pt = pass + tjs[e];
            U1e[e] = S.preU1[pt]; C1e[e] = S.preC1[pt];
            U2e[e] = S.preU2[pt]; C2e[e] = S.preC2[pt];
            IBe[e] = S.preIB[pt]; NAe[e] = S.preNA[pt];
        }
        #pragma unroll 4
        for (int rl = 0; rl < 16; rl++) {
            const int r = w * 16 + rl;
            if (S.rowt[r] != pass) continue;         // row handled in other pass
            const float4 r4 = __ldg(reinterpret_cast<const float4*>(dbase + (size_t)rl * rowN));
            float sp = 0.f, sr = 0.f;
            const float rv4[4] = {r4.x, r4.y, r4.z, r4.w};
            #pragma unroll
            for (int e = 0; e < 4; e++) {
                const float rv = rv4[e];
                const float x  = fma_sat(rv, IBe[e], NAe[e]);
                const float fc = fmaf(x * x, fmaf(2.0f, x, -3.0f), 1.0f);
                const float t1 = fc * ex2_approx(fmaf(U1e[e], rv, C1e[e]));
                const float t2 = fc * ex2_approx(fmaf(U2e[e], rv, C2e[e]));
                sp += t1; sr += t2;
                if (!DIAG) { colphi[e] += t1; colrho[e] += t2; }
            }
            S.srow[r][lane] = make_float2(sp, sr);
        }
    }
    if (!DIAG) {
        #pragma unroll
        for (int e = 0; e < 4; e++) {
            atomicAdd(&S.scolphi[lane * 4 + e], colphi[e]);
            atomicAdd(&S.scolrho[lane * 4 + e], colrho[e]);
        }
    }
}

__global__ void __launch_bounds__(256)
eam_sym_kernel(const float* __restrict__ dist,      // [B,N,N]
               const int*   __restrict__ types,     // [B,N]
               const float* __restrict__ A,  const float* __restrict__ p,
               const float* __restrict__ xi, const float* __restrict__ q,
               const float* __restrict__ r0, const float* __restrict__ cut_a,
               const float* __restrict__ cut_b,
               const float* __restrict__ emb_scale,
               const float* __restrict__ offset,
               int N, int B, int ntile, int perB,   // perB = ntile*(ntile+1)/2
               float* __restrict__ out)
{
    __shared__ TileSmem S;
    const int tid  = threadIdx.x;
    const int lane = tid & 31;
    const int w    = tid >> 5;

    const int b = blockIdx.x / perB;
    int u = blockIdx.x % perB;
    int ti = 0;
    while (u >= ntile - ti) { u -= ntile - ti; ti++; }
    const int tj   = ti + u;
    const bool diag = (ti == tj);
    const int rowbase = ti * 128;
    const int colbase = tj * 128;
    const int* __restrict__ tb = types + (size_t)b * N;

    if (tid < 3) {       // per-pair-type constants (3 pts for NT==2)
        const int pt = tid;
        const float L2E = 1.4426950408889634f;
        const float pv = p[pt], qv = q[pt], r0v = r0[pt];
        const float av = cut_a[pt], bv = cut_b[pt];
        const float ib = 1.0f / (bv - av);
        S.preU1[pt] = -pv * L2E / r0v;
        S.preC1[pt] =  pv * L2E + __log2f(A[pt]);
        S.preU2[pt] = -2.0f * qv * L2E / r0v;
        S.preC2[pt] =  2.0f * qv * L2E + 2.0f * __log2f(xi[pt]);
        S.preIB[pt] = ib;
        S.preNA[pt] = -av * ib;
    }
    if (tid < 128) {
        S.rowt[tid]    = tb[rowbase + tid];
        S.scolphi[tid] = 0.f;
        S.scolrho[tid] = 0.f;
    }
    __syncthreads();

    // this lane's 4 column types (fixed for whole tile)
    const int4 tj4 = reinterpret_cast<const int4*>(tb + colbase)[lane];
    const float* dbase = dist + ((size_t)(b * N + rowbase + w * 16)) * N + colbase + lane * 4;

    if (diag) tile_work<true >(S, dbase, tj4, w, lane, (size_t)N);
    else      tile_work<false>(S, dbase, tj4, w, lane, (size_t)N);
    __syncthreads();

    // flush row sums (threads 0..127) and column sums (threads 128..255)
    if (tid < 128) {
        float sp = 0.f, sr = 0.f;
        #pragma unroll 8
        for (int l = 0; l < 32; l++) {
            const float2 v = S.srow[tid][l];
            sp += v.x; sr += v.y;
        }
        const size_t g = (size_t)b * N + rowbase + tid;
        atomicAdd(&g_phi[g], f2fix(sp));
        atomicAdd(&g_rho[g], f2fix(sr));
    } else if (!diag) {
        const int c = tid - 128;
        const size_t g = (size_t)b * N + colbase + c;
        atomicAdd(&g_phi[g], f2fix(S.scolphi[c]));
        atomicAdd(&g_rho[g], f2fix(S.scolrho[c]));
    }

    // ── per-batch ticket: last block of batch b finalizes batch b ──
    __threadfence();
    __syncthreads();
    __shared__ unsigned int rank_s;
    if (tid == 0) rank_s = atomicAdd(&g_ticket_b[b], 1u);
    __syncthreads();
    if (rank_s != (unsigned)(perB - 1)) return;
    __threadfence();

    long long esum = 0; int csum = 0;
    for (int a2 = tid; a2 < N; a2 += 256) {
        const size_t g = (size_t)b * N + a2;
        const long long ph = (long long)__ldcg(&g_phi[g]);
        const long long rh = (long long)__ldcg(&g_rho[g]);
        g_phi[g] = 0ull; g_rho[g] = 0ull;            // reset for next replay
        const float sp = (float)((double)ph / FIX_SCALE);
        const float sr = (float)((double)rh / FIX_SCALE);
        const int   t  = tb[a2];
        const float emb = fmaf(-emb_scale[t], sqrtf(fmaxf(sr, 0.0f)), offset[t]);
        const float ae  = fmaf(0.5f, sp, emb);
        esum += (long long)__float2ll_rn(ae * (float)FIX_SCALE);
        if (t >= 0) csum++;
    }
    #pragma unroll
    for (int o = 16; o > 0; o >>= 1) {
        esum += __shfl_down_sync(0xFFFFFFFFu, esum, o);
        csum += __shfl_down_sync(0xFFFFFFFFu, csum, o);
    }
    __shared__ long long eb[8];
    __shared__ int       cb[8];
    if (lane == 0) { eb[w] = esum; cb[w] = csum; }
    __syncthreads();
    if (w == 0) {
        esum = (lane < 8) ? eb[lane] : 0ll;
        csum = (lane < 8) ? cb[lane] : 0;
        #pragma unroll
        for (int o = 4; o > 0; o >>= 1) {
            esum += __shfl_down_sync(0xFFFFFFFFu, esum, o);
            csum += __shfl_down_sync(0xFFFFFFFFu, csum, o);
        }
        if (lane == 0) {
            const float E = (float)((double)esum / FIX_SCALE);
            out[2 * b]     = E;
            out[2 * b + 1] = E / (float)csum;
            g_ticket_b[b]  = 0u;                     // reset ticket
        }
    }
}

// ───────────────────────── generic fallback ─────────────────────────

__global__ void __launch_bounds__(256)
eam_warp_kernel(const float* __restrict__ dist, const int* __restrict__ types,
                const float* __restrict__ A,  const float* __restrict__ p,
                const float* __restrict__ xi, const float* __restrict__ q,
                const float* __restrict__ r0, const float* __restrict__ cut_a,
                const float* __restrict__ cut_b,
                const float* __restrict__ emb_scale,
                const float* __restrict__ offset, int N, int NT, int BN)
{
    const int lane = threadIdx.x & 31;
    const int row  = blockIdx.x * (blockDim.x >> 5) + (threadIdx.x >> 5);
    if (row >= BN) return;
    const int b    = row / N;
    const int t_i  = types[row];
    const float L2E = 1.4426950408889634f;
    float sphi = 0.0f, srho = 0.0f;
    for (int j = lane; j < N; j += 32) {
        const int pt = pair_type(t_i, types[(size_t)b * N + j], NT);
        const float r = dist[(size_t)row * N + j];
        const float ib = 1.0f / (cut_b[pt] - cut_a[pt]);
        const float x = fma_sat(r, ib, -cut_a[pt] * ib);
        const float fc = fmaf(x * x, fmaf(2.0f, x, -3.0f), 1.0f);
        const float rn = r / r0[pt] - 1.0f;
        sphi = fmaf(A[pt] * fc, ex2_approx(-p[pt] * L2E * rn), sphi);
        srho = fmaf(xi[pt] * xi[pt] * fc, ex2_approx(-2.0f * q[pt] * L2E * rn), srho);
    }
    #pragma unroll
    for (int o = 16; o > 0; o >>= 1) {
        sphi += __shfl_down_sync(0xFFFFFFFFu, sphi, o);
        srho += __shfl_down_sync(0xFFFFFFFFu, srho, o);
    }
    if (lane == 0) {
        const float emb = fmaf(-emb_scale[t_i], sqrtf(srho), offset[t_i]);
        const float ae  = fmaf(0.5f, sphi, emb);
        atomicAdd(reinterpret_cast<unsigned long long*>(&g_energy_fix[b]),
                  (unsigned long long)(long long)__float2ll_rn(ae * (float)FIX_SCALE));
        if (t_i >= 0) atomicAdd(&g_count[b], 1);
    }
}

__global__ void eam_finalize_kernel(float* __restrict__ out, int B)
{
    const int i = threadIdx.x;
    if (i < B) {
        const float E = (float)((double)g_energy_fix[i] / FIX_SCALE);
        out[2 * i]     = E;
        out[2 * i + 1] = E / (float)g_count[i];
        g_energy_fix[i] = 0;
        g_count[i]      = 0;
    }
}

// ───────────────────────────── launcher ─────────────────────────────

extern "C" void kernel_launch(void* const* d_in, const int* in_sizes, int n_in,
                              void* d_out, int out_size)
{
    const float* dist      = (const float*)d_in[0];
    const float* A         = (const float*)d_in[1];
    const float* p         = (const float*)d_in[2];
    const float* xi        = (const float*)d_in[3];
    const float* q         = (const float*)d_in[4];
    const float* r0        = (const float*)d_in[5];
    const float* cut_a     = (const float*)d_in[6];
    const float* cut_b     = (const float*)d_in[7];
    const float* emb_scale = (const float*)d_in[8];
    const float* offset    = (const float*)d_in[9];
    const int*   types     = (const int*)d_in[10];
    float* out = (float*)d_out;

    const long long dist_sz  = in_sizes[0];   // B*N*N
    const long long types_sz = in_sizes[10];  // B*N
    const int N   = (int)(dist_sz / types_sz);
    const int B   = (int)(types_sz / N);
    const int NT  = in_sizes[8];
    const int NPT = in_sizes[1];
    const int BN  = B * N;

    const bool fast = (NT == 2) && (NPT >= 3) && (B >= 1) && (B <= MAX_B) &&
                      (BN <= MAX_BN) && (N % 128 == 0) &&
                      (((uintptr_t)dist & 15u) == 0) && (((uintptr_t)types & 15u) == 0);

    if (fast) {
        const int ntile = N / 128;
        const int perB  = ntile * (ntile + 1) / 2;
        eam_sym_kernel<<<B * perB, 256>>>(dist, types, A, p, xi, q, r0,
                                          cut_a, cut_b, emb_scale, offset,
                                          N, B, ntile, perB, out);
    } else {
        const int warps_per_block = 8;
        const int nblocks = (BN + warps_per_block - 1) / warps_per_block;
        eam_warp_kernel<<<nblocks, warps_per_block * 32>>>(
            dist, types, A, p, xi, q, r0, cut_a, cut_b, emb_scale, offset,
            N, NT, BN);
        eam_finalize_kernel<<<1, 64>>>(out, B);
    }
}